// round 2
// baseline (speedup 1.0000x reference)
#include <cuda_runtime.h>

#define LH 128
#define LP 32
#define DM 64
#define HID 64
#define MAXLEN 128
#define ST 68   // smem row stride (floats), 16B-aligned, conflict-avoiding

typedef unsigned long long u64;

__device__ __forceinline__ u64 pk2(float lo, float hi) {
    u64 r; asm("mov.b64 %0,{%1,%2};" : "=l"(r) : "f"(lo), "f"(hi)); return r;
}
__device__ __forceinline__ void fma2(u64& d, u64 a, u64 b) {
    asm("fma.rn.f32x2 %0,%1,%2,%3;" : "=l"(d) : "l"(a), "l"(b), "l"(d));
}
__device__ __forceinline__ void mul2(u64& d, u64 a, u64 b) {
    asm("mul.rn.f32x2 %0,%1,%2;" : "=l"(d) : "l"(a), "l"(b));
}
__device__ __forceinline__ float2 up2(u64 v) {
    float2 r; asm("mov.b64 {%0,%1},%2;" : "=f"(r.x), "=f"(r.y) : "l"(v)); return r;
}

// smem layout (floats)
#define O_X  0                    // [128][ST] hla input -> h1 halves
#define O_C  (O_X + LH*ST)        // [128][ST] LN(ctx) -> z (residual)
#define O_Q  (O_C + LH*ST)        // [128][ST] projected q (parked for residual)
#define O_P  (O_Q + LH*ST)        // [32][ST]  pep input
#define O_KV (O_P + LP*ST)        // [32][ST]  kv
#define O_W  (O_KV + LP*ST)       // [64][ST]  current weight panel
#define SMEM_FLOATS (O_W + 64*ST)
#define SMEM_BYTES  (SMEM_FLOATS * 4)

// Load a [64 x 64] weight panel from gmem (row length rowlen, starting col col0)
// into s_w[k][n], k-major. 1024 float4s over 512 threads.
__device__ __forceinline__ void load_w(float* sw, const float* __restrict__ g,
                                       int rowlen, int col0, int t) {
    #pragma unroll
    for (int v = 0; v < 2; v++) {
        int idx = v * 512 + t;
        int k = idx >> 4, c4 = idx & 15;
        *(float4*)&sw[k * ST + c4 * 4] =
            *(const float4*)&g[k * rowlen + col0 + c4 * 4];
    }
}

__device__ __forceinline__ void init_acc2(u64 acc[2][4], const float* __restrict__ bias, int n0) {
    float4 b0 = *(const float4*)&bias[n0];
    float4 b1 = *(const float4*)&bias[n0 + 4];
    u64 p0 = pk2(b0.x, b0.y), p1 = pk2(b0.z, b0.w);
    u64 p2 = pk2(b1.x, b1.y), p3 = pk2(b1.z, b1.w);
    acc[0][0] = p0; acc[0][1] = p1; acc[0][2] = p2; acc[0][3] = p3;
    acc[1][0] = p0; acc[1][1] = p1; acc[1][2] = p2; acc[1][3] = p3;
}

// Tiled GEMM: out[m0..m0+ROWS-1][n0..n0+7] += A[m][k] * W[k][n], K steps.
// A row-major (stride ST), W k-major (stride ST). acc pairs packed along n.
template<int K, int ROWS>
__device__ __forceinline__ void gemm_rx8(const float* __restrict__ sA, int m0,
                                         const float* __restrict__ sW, int n0,
                                         u64 acc[][4]) {
    #pragma unroll 4
    for (int k0 = 0; k0 < K; k0 += 4) {
        float4 ar[ROWS];
        #pragma unroll
        for (int r = 0; r < ROWS; r++)
            ar[r] = *(const float4*)&sA[(m0 + r) * ST + k0];
        #pragma unroll
        for (int j = 0; j < 4; j++) {
            const float* wr = &sW[(k0 + j) * ST + n0];
            ulonglong2 b01 = *(const ulonglong2*)wr;
            ulonglong2 b23 = *(const ulonglong2*)(wr + 4);
            #pragma unroll
            for (int r = 0; r < ROWS; r++) {
                float av = (j == 0) ? ar[r].x : (j == 1) ? ar[r].y
                         : (j == 2) ? ar[r].z : ar[r].w;
                u64 d = pk2(av, av);
                fma2(acc[r][0], d, b01.x);
                fma2(acc[r][1], d, b01.y);
                fma2(acc[r][2], d, b23.x);
                fma2(acc[r][3], d, b23.y);
            }
        }
    }
}

// Store one thread's 2x8 acc tile to smem rows (row-major, float4 stores).
__device__ __forceinline__ void store_tile2(float* dst, int m0, int n0, u64 acc[2][4]) {
    #pragma unroll
    for (int r = 0; r < 2; r++) {
        float2 f0 = up2(acc[r][0]), f1 = up2(acc[r][1]);
        float2 f2 = up2(acc[r][2]), f3 = up2(acc[r][3]);
        *(float4*)&dst[(m0 + r) * ST + n0]     = make_float4(f0.x, f0.y, f1.x, f1.y);
        *(float4*)&dst[(m0 + r) * ST + n0 + 4] = make_float4(f2.x, f2.y, f3.x, f3.y);
    }
}

__global__ __launch_bounds__(512, 1)
void h2p_kernel(const float* __restrict__ hla_in,
                const float* __restrict__ pep_in,
                const float* __restrict__ W_hla, const float* __restrict__ b_hla,
                const float* __restrict__ W_pep, const float* __restrict__ b_pep,
                const float* __restrict__ rel_bias,
                const float* __restrict__ ln_g, const float* __restrict__ ln_b,
                const float* __restrict__ W1, const float* __restrict__ b1,
                const float* __restrict__ W2, const float* __restrict__ b2,
                const float* __restrict__ W_out, const float* __restrict__ b_out,
                float* __restrict__ out)
{
    extern __shared__ float sm[];
    const int t  = threadIdx.x;
    const int bb = blockIdx.x;
    const int m0 = (t >> 3) * 2;     // 2 rows per thread (0..126)
    const int n0 = (t & 7) * 8;      // 8 cols per thread (0..56)

    const float* hla_b = hla_in + (size_t)bb * (LH * DM);
    const float* pep_b = pep_in + (size_t)bb * (LP * DM);

    // ---- stage hla [128][64], pep [32][64], W_pep panel ----
    {
        const float4* g4 = (const float4*)hla_b;
        #pragma unroll
        for (int i = 0; i < 4; i++) {
            int idx = i * 512 + t;
            int r = idx >> 4, c4 = idx & 15;
            *(float4*)&sm[O_X + r * ST + c4 * 4] = g4[idx];
        }
        const float4* p4 = (const float4*)pep_b;
        int r = t >> 4, c4 = t & 15;
        *(float4*)&sm[O_P + r * ST + c4 * 4] = p4[t];
    }
    load_w(sm + O_W, W_pep, HID, 0, t);
    __syncthreads();

    // ---- kv = pep @ W_pep + b_pep (threads 0..255, 1x8 tiles) ----
    if (t < 256) {
        int km = t >> 3;
        int kn = (t & 7) * 8;
        u64 kacc[1][4];
        {
            float4 b0 = *(const float4*)&b_pep[kn];
            float4 b1 = *(const float4*)&b_pep[kn + 4];
            kacc[0][0] = pk2(b0.x, b0.y); kacc[0][1] = pk2(b0.z, b0.w);
            kacc[0][2] = pk2(b1.x, b1.y); kacc[0][3] = pk2(b1.z, b1.w);
        }
        gemm_rx8<DM, 1>(sm + O_P, km, sm + O_W, kn, kacc);
        float2 f0 = up2(kacc[0][0]), f1 = up2(kacc[0][1]);
        float2 f2 = up2(kacc[0][2]), f3 = up2(kacc[0][3]);
        *(float4*)&sm[O_KV + km * ST + kn]     = make_float4(f0.x, f0.y, f1.x, f1.y);
        *(float4*)&sm[O_KV + km * ST + kn + 4] = make_float4(f2.x, f2.y, f3.x, f3.y);
    }
    __syncthreads();
    load_w(sm + O_W, W_hla, HID, 0, t);
    __syncthreads();

    // ---- q = hla @ W_hla + b_hla -> s_q ----
    {
        u64 qa[2][4];
        init_acc2(qa, b_hla, n0);
        gemm_rx8<DM, 2>(sm + O_X, m0, sm + O_W, n0, qa);
        store_tile2(sm + O_Q, m0, n0, qa);
    }
    __syncthreads();

    // preload W1 panel A for the FFN while attention runs
    load_w(sm + O_W, W1, 2 * HID, 0, t);

    // ---- attention + LayerNorm: thread = (row r, head h) ----
    {
        const int r = t >> 2, h = t & 3;
        const float* qrow = sm + O_Q + r * ST + h * 16;
        ulonglong2 qA = *(const ulonglong2*)(qrow + 0);
        ulonglong2 qB = *(const ulonglong2*)(qrow + 4);
        ulonglong2 qC = *(const ulonglong2*)(qrow + 8);
        ulonglong2 qD = *(const ulonglong2*)(qrow + 12);

        float sc[32];
        const float* brow = rel_bias + h * (MAXLEN * MAXLEN) + r * MAXLEN;
        #pragma unroll
        for (int k4 = 0; k4 < 8; k4++) {
            float4 bv = __ldg((const float4*)&brow[k4 * 4]);
            sc[k4*4+0] = bv.x; sc[k4*4+1] = bv.y; sc[k4*4+2] = bv.z; sc[k4*4+3] = bv.w;
        }
        #pragma unroll
        for (int k = 0; k < LP; k++) {
            const float* kr = sm + O_KV + k * ST + h * 16;
            ulonglong2 v0 = *(const ulonglong2*)(kr + 0);
            ulonglong2 v1 = *(const ulonglong2*)(kr + 4);
            ulonglong2 v2 = *(const ulonglong2*)(kr + 8);
            ulonglong2 v3 = *(const ulonglong2*)(kr + 12);
            u64 s;
            mul2(s, qA.x, v0.x);
            fma2(s, qA.y, v0.y);
            fma2(s, qB.x, v1.x);
            fma2(s, qB.y, v1.y);
            fma2(s, qC.x, v2.x);
            fma2(s, qC.y, v2.y);
            fma2(s, qD.x, v3.x);
            fma2(s, qD.y, v3.y);
            float2 sp = up2(s);
            sc[k] = fmaf(0.25f, sp.x + sp.y, sc[k]);
        }
        // softmax over 32 keys
        float mx = sc[0];
        #pragma unroll
        for (int k = 1; k < LP; k++) mx = fmaxf(mx, sc[k]);
        float ssum = 0.f;
        #pragma unroll
        for (int k = 0; k < LP; k++) { sc[k] = __expf(sc[k] - mx); ssum += sc[k]; }
        float inv = 1.0f / ssum;

        u64 cx[8];
        #pragma unroll
        for (int i = 0; i < 8; i++) cx[i] = 0ull;
        #pragma unroll
        for (int k = 0; k < LP; k++) {
            const float* kr = sm + O_KV + k * ST + h * 16;
            ulonglong2 v0 = *(const ulonglong2*)(kr + 0);
            ulonglong2 v1 = *(const ulonglong2*)(kr + 4);
            ulonglong2 v2 = *(const ulonglong2*)(kr + 8);
            ulonglong2 v3 = *(const ulonglong2*)(kr + 12);
            u64 pd = pk2(sc[k], sc[k]);
            fma2(cx[0], pd, v0.x); fma2(cx[1], pd, v0.y);
            fma2(cx[2], pd, v1.x); fma2(cx[3], pd, v1.y);
            fma2(cx[4], pd, v2.x); fma2(cx[5], pd, v2.y);
            fma2(cx[6], pd, v3.x); fma2(cx[7], pd, v3.y);
        }
        float x[16];
        #pragma unroll
        for (int i = 0; i < 8; i++) {
            float2 f = up2(cx[i]);
            x[2*i]   = f.x * inv;
            x[2*i+1] = f.y * inv;
        }
        // LayerNorm over full row (4 threads cooperate via shfl)
        float s1 = 0.f, s2 = 0.f;
        #pragma unroll
        for (int i = 0; i < 16; i++) { s1 += x[i]; s2 = fmaf(x[i], x[i], s2); }
        s1 += __shfl_xor_sync(0xffffffffu, s1, 1);
        s2 += __shfl_xor_sync(0xffffffffu, s2, 1);
        s1 += __shfl_xor_sync(0xffffffffu, s1, 2);
        s2 += __shfl_xor_sync(0xffffffffu, s2, 2);
        float mu   = s1 * (1.0f / 64.0f);
        float var  = s2 * (1.0f / 64.0f) - mu * mu;
        float rstd = rsqrtf(var + 1e-5f);
        #pragma unroll
        for (int c4 = 0; c4 < 4; c4++) {
            float4 gv = __ldg((const float4*)&ln_g[h * 16 + c4 * 4]);
            float4 bv = __ldg((const float4*)&ln_b[h * 16 + c4 * 4]);
            float4 o;
            o.x = (x[c4*4+0] - mu) * rstd * gv.x + bv.x;
            o.y = (x[c4*4+1] - mu) * rstd * gv.y + bv.y;
            o.z = (x[c4*4+2] - mu) * rstd * gv.z + bv.z;
            o.w = (x[c4*4+3] - mu) * rstd * gv.w + bv.w;
            *(float4*)&sm[O_C + r * ST + h * 16 + c4 * 4] = o;
        }
    }
    __syncthreads();

    // ---- FFN: two 64-col halves; out acc persists across both ----
    u64 oacc[2][4];
    init_acc2(oacc, b2, n0);

    // pass A: h1a = gelu(LN_ctx @ W1[:, :64] + b1[:64]) -> s_x
    {
        u64 hacc[2][4];
        init_acc2(hacc, b1, n0);
        gemm_rx8<HID, 2>(sm + O_C, m0, sm + O_W, n0, hacc);
        #pragma unroll
        for (int r = 0; r < 2; r++) {
            #pragma unroll
            for (int p = 0; p < 4; p++) {
                float2 f = up2(hacc[r][p]);
                f.x *= normcdff(f.x);
                f.y *= normcdff(f.y);
                hacc[r][p] = pk2(f.x, f.y);
            }
        }
        store_tile2(sm + O_X, m0, n0, hacc);
    }
    __syncthreads();
    load_w(sm + O_W, W2, HID, 0, t);           // W2 rows 0..63
    __syncthreads();
    gemm_rx8<HID, 2>(sm + O_X, m0, sm + O_W, n0, oacc);
    __syncthreads();
    load_w(sm + O_W, W1, 2 * HID, HID, t);     // W1 cols 64..127
    __syncthreads();

    // pass B: h1b -> s_x
    {
        u64 hacc[2][4];
        init_acc2(hacc, b1, HID + n0);
        gemm_rx8<HID, 2>(sm + O_C, m0, sm + O_W, n0, hacc);
        #pragma unroll
        for (int r = 0; r < 2; r++) {
            #pragma unroll
            for (int p = 0; p < 4; p++) {
                float2 f = up2(hacc[r][p]);
                f.x *= normcdff(f.x);
                f.y *= normcdff(f.y);
                hacc[r][p] = pk2(f.x, f.y);
            }
        }
        store_tile2(sm + O_X, m0, n0, hacc);
    }
    __syncthreads();
    load_w(sm + O_W, W2 + HID * HID, HID, 0, t);   // W2 rows 64..127
    __syncthreads();
    gemm_rx8<HID, 2>(sm + O_X, m0, sm + O_W, n0, oacc);
    __syncthreads();

    // ---- residual z = q + ffn -> s_c ----
    #pragma unroll
    for (int r = 0; r < 2; r++) {
        float4 q0 = *(const float4*)&sm[O_Q + (m0 + r) * ST + n0];
        float4 q1 = *(const float4*)&sm[O_Q + (m0 + r) * ST + n0 + 4];
        float2 f0 = up2(oacc[r][0]), f1 = up2(oacc[r][1]);
        float2 f2 = up2(oacc[r][2]), f3 = up2(oacc[r][3]);
        *(float4*)&sm[O_C + (m0 + r) * ST + n0] =
            make_float4(q0.x + f0.x, q0.y + f0.y, q0.z + f1.x, q0.w + f1.y);
        *(float4*)&sm[O_C + (m0 + r) * ST + n0 + 4] =
            make_float4(q1.x + f2.x, q1.y + f2.y, q1.z + f3.x, q1.w + f3.y);
    }
    load_w(sm + O_W, W_out, DM, 0, t);
    __syncthreads();

    // ---- out = z @ W_out + b_out ----
    {
        u64 yacc[2][4];
        init_acc2(yacc, b_out, n0);
        gemm_rx8<HID, 2>(sm + O_C, m0, sm + O_W, n0, yacc);
        float* op = out + ((size_t)bb * LH) * DM;
        #pragma unroll
        for (int r = 0; r < 2; r++) {
            float2 f0 = up2(yacc[r][0]), f1 = up2(yacc[r][1]);
            float2 f2 = up2(yacc[r][2]), f3 = up2(yacc[r][3]);
            *(float4*)&op[(m0 + r) * DM + n0] =
                make_float4(f0.x, f0.y, f1.x, f1.y);
            *(float4*)&op[(m0 + r) * DM + n0 + 4] =
                make_float4(f2.x, f2.y, f3.x, f3.y);
        }
    }
}

extern "C" void kernel_launch(void* const* d_in, const int* in_sizes, int n_in,
                              void* d_out, int out_size)
{
    const float* hla_in   = (const float*)d_in[0];
    const float* pep_in   = (const float*)d_in[1];
    const float* W_hla    = (const float*)d_in[2];
    const float* b_hla    = (const float*)d_in[3];
    const float* W_pep    = (const float*)d_in[4];
    const float* b_pep    = (const float*)d_in[5];
    const float* rel_bias = (const float*)d_in[6];
    const float* ln_g     = (const float*)d_in[7];
    const float* ln_b     = (const float*)d_in[8];
    const float* W1       = (const float*)d_in[9];
    const float* b1       = (const float*)d_in[10];
    const float* W2       = (const float*)d_in[11];
    const float* b2       = (const float*)d_in[12];
    const float* W_out    = (const float*)d_in[13];
    const float* b_out    = (const float*)d_in[14];
    float* out = (float*)d_out;

    int B = in_sizes[0] / (LH * DM);

    cudaFuncSetAttribute(h2p_kernel, cudaFuncAttributeMaxDynamicSharedMemorySize, SMEM_BYTES);
    h2p_kernel<<<B, 512, SMEM_BYTES>>>(hla_in, pep_in, W_hla, b_hla, W_pep, b_pep,
                                       rel_bias, ln_g, ln_b, W1, b1, W2, b2,
                                       W_out, b_out, out);
}